// round 17
// baseline (speedup 1.0000x reference)
#include <cuda_runtime.h>
#include <math.h>

#define NN 10000
#define NSLICE 28
#define NCHUNK 5
#define NB 140
#define NT 1024
#define OUTB 2000              // outputs per chunk (500 quads)
#define TW2 200                // u16 row width
#define TABW 19904             // u32 words per global table (padded +4)
#define COPYW 11904            // u32 words per smem copy (>= 119*100 + shift)
#define COPYB (COPYW * 4)      // 47616 bytes per copy
#define SLIST_OFF (4 * COPYB)  // 190464
#define SLIST_MAX 512
#define COMB_OFF (SLIST_OFF + SLIST_MAX * 4)       // 192512
#define SMEM_BYTES (COMB_OFF + 512 * 16)           // 200704
#define QSCALE 448.0
#define SSCALE 512.0

// ---------------------------------------------------------------------------
// Compile-time tables (same size as the R15 build that compiled): tA = even-
// aligned u16 pairs, tB = shifted by one u16; Ai = integer A rows (x512).
// ---------------------------------------------------------------------------
constexpr double csqrt(double x) {
    if (x <= 0.0) return 0.0;
    double r = 1.0;
    while (r * r < x) r *= 2.0;
    for (int i = 0; i < 8; ++i) r = 0.5 * (r + x / r);
    return r;
}

struct alignas(16) Tables {
    unsigned tA[TABW];         // tA[u] = v[2u] | v[2u+1]<<16
    unsigned tB[TABW];         // tB[u] = v[2u+1] | v[2u+2]<<16
    unsigned Ai[NN];           // round(A * 512)
};

constexpr Tables make_tables() {
    Tables T{};
    unsigned short v[39812] = {};
    for (int t = 0; t < 39800; ++t) {
        int a = t / TW2, c = t - a * TW2;
        double dx = (double)(a - 99), dy = (double)(c - 99);
        v[t] = (unsigned short)(csqrt(dx * dx + dy * dy) * QSCALE + 0.5);
    }
    for (int w = 0; w < 19900; ++w) {
        T.tA[w] = (unsigned)v[2 * w] | ((unsigned)v[2 * w + 1] << 16);
        T.tB[w] = (unsigned)v[2 * w + 1] | ((unsigned)v[2 * w + 2] << 16);
    }
    for (int di = 0; di < 100; ++di) {
        double pref[100] = {};
        double run = 0.0;
        for (int d = 1; d < 100; ++d) {
            run += csqrt((double)(di * di + d * d));
            pref[d] = run;
        }
        for (int j = 0; j < 100; ++j) {
            double a = (double)di + pref[j] + pref[99 - j];
            T.Ai[di * 100 + j] = (unsigned)(a * SSCALE + 0.5);
        }
    }
    return T;
}

__device__ const Tables c_tab = make_tables();

__device__ unsigned g_Ti[10240];   // integer T accumulators (zero-init, self-cleaning)
__device__ unsigned g_Si[10240];   // integer S accumulators
__device__ float g_cs[NCHUNK];
__device__ int   g_dc[NCHUNK];
__device__ int   g_done2;

__global__ __launch_bounds__(NT, 1) void k_all(const float* __restrict__ prob,
                                               const float* __restrict__ gt,
                                               float* __restrict__ out) {
    extern __shared__ unsigned char smraw[];
    unsigned* cp0 = (unsigned*)smraw;
    unsigned* cp1 = (unsigned*)(smraw + COPYB);
    unsigned* cp2 = (unsigned*)(smraw + 2 * COPYB);
    unsigned* cp3 = (unsigned*)(smraw + 3 * COPYB);
    int* slist = (int*)(smraw + SLIST_OFF);
    unsigned* comb = (unsigned*)(smraw + COMB_OFF);

    __shared__ int swtot[32];
    __shared__ int swoff[32];
    __shared__ int sh_n;
    __shared__ int lastFlag;
    __shared__ float wsum[32];

    const int bid = blockIdx.x;
    const int tid = threadIdx.x;
    const int warp = tid >> 5, lane = tid & 31;

    const int chunk = bid / NSLICE;
    const int s = bid - chunk * NSLICE;
    const int o0 = chunk * OUTB;
    const int i1lo = 20 * chunk;
    const int rlo = 80 - 20 * chunk;

    // ---- gt loads first (MLP=10); latency hides under staging ----
    float vv[10];
    const int o_base = warp * 320 + lane;
    #pragma unroll
    for (int it = 0; it < 10; ++it) {
        int o = o_base + it * 32;
        vv[it] = (o < NN) ? gt[o] : 0.0f;
    }
    if (tid < 63) {
        const char* p = (const char*)(prob + chunk * OUTB) + tid * 128;
        asm volatile("prefetch.global.L2 [%0];" :: "l"(p));
    }

    // ---- stage copies 0/1 from global (16B loads) ----
    {
        int wordoff = rlo * 100;             // multiple of 4
        const int4* s0 = (const int4*)(c_tab.tA + wordoff);
        const int4* s1 = (const int4*)(c_tab.tB + wordoff);
        int4* d0 = (int4*)cp0;
        int4* d1 = (int4*)cp1;
        for (int k2 = tid; k2 < COPYW / 4; k2 += NT) {
            d0[k2] = s0[k2];
            d1[k2] = s1[k2];
        }
    }

    // ---- compaction ballots (independent of staging) ----
    unsigned bal[10];
    #pragma unroll
    for (int it = 0; it < 10; ++it) {
        int o = o_base + it * 32;
        bool p = (o < NN) && (vv[it] >= 0.5f);
        bal[it] = __ballot_sync(0xffffffffu, p);
    }
    int pre[10]; int run = 0;
    #pragma unroll
    for (int it = 0; it < 10; ++it) { pre[it] = run; run += __popc(bal[it]); }
    if (lane == 0) swtot[warp] = run;
    __syncthreads();
    if (warp == 0) {
        int t = swtot[lane];
        int incl = t;
        #pragma unroll
        for (int d = 1; d < 32; d <<= 1) {
            int v = __shfl_up_sync(0xffffffffu, incl, d);
            if (lane >= d) incl += v;
        }
        swoff[lane] = incl - t;
        if (lane == 31) sh_n = incl;
    }
    __syncthreads();

    // ---- build shifted copies 2/3 from 0/1 (one-word shift) ----
    for (int w = tid; w < COPYW; w += NT) {
        int w1 = (w + 1 < COPYW) ? (w + 1) : w;
        cp2[w] = cp0[w1];
        cp3[w] = cp1[w1];
    }

    const int n = sh_n;
    const int e0 = (s * n) / NSLICE;
    const int e1 = ((s + 1) * n) / NSLICE;
    const int cnt = e1 - e0;
    {
        int base = swoff[warp];
        #pragma unroll
        for (int it = 0; it < 10; ++it) {
            unsigned b = bal[it];
            if ((b >> lane) & 1u) {
                int pos = base + pre[it] + __popc(b & ((1u << lane) - 1u));
                if (pos >= e0 && pos < e1) {
                    int o = o_base + it * 32;
                    int i2 = o / 100, j2 = o - i2 * 100;
                    int Fu = (i2 + 99 - rlo) * TW2 + (j2 + 99);
                    int r = (Fu - 3) & 3;
                    slist[pos - e0] = r * COPYB + 2 * (Fu - 3 - r);
                }
            }
        }
    }
    __syncthreads();

    // ---- main sparse DP2A accumulate: 4 outputs/thread, list split ----
    int h4 = (cnt / 2 + 3) & ~3;
    if (h4 > cnt) h4 = cnt;
    bool isLow = (tid < 500);
    bool isUp  = (tid >= 512 && tid < 1012);
    int q = isLow ? tid : (tid - 512);
    if (!(isLow || isUp)) q = 0;
    int i1 = q / 25 + i1lo;
    int j1q = 4 * (q - (q / 25) * 25);
    int m = i1 * TW2 + j1q;                  // multiple of 4

    unsigned baseA;
    asm("{ .reg .u64 t; cvta.to.shared.u64 t, %1; cvt.u32.u64 %0, t; }"
        : "=r"(baseA) : "l"(smraw));
    unsigned tb = baseA - 2u * (unsigned)m;

    unsigned a0 = 0, a1 = 0, a2 = 0, a3 = 0;
    int kb = isUp ? h4 : 0;
    int ke = isLow ? h4 : (isUp ? cnt : 0);
    int k = kb;
    int k4e = kb + ((ke - kb) & ~3);
    for (; k < k4e; k += 4) {
        int4 e = *(const int4*)(slist + k);
        unsigned lo0, hi0, lo1, hi1, lo2, hi2, lo3, hi3;
        asm("ld.shared.v2.u32 {%0,%1},[%2];" : "=r"(lo0), "=r"(hi0) : "r"(tb + (unsigned)e.x));
        asm("ld.shared.v2.u32 {%0,%1},[%2];" : "=r"(lo1), "=r"(hi1) : "r"(tb + (unsigned)e.y));
        asm("ld.shared.v2.u32 {%0,%1},[%2];" : "=r"(lo2), "=r"(hi2) : "r"(tb + (unsigned)e.z));
        asm("ld.shared.v2.u32 {%0,%1},[%2];" : "=r"(lo3), "=r"(hi3) : "r"(tb + (unsigned)e.w));
        // output d uses u16 at t_start+3-d: d0=hi16(hi), d1=lo16(hi), d2=hi16(lo), d3=lo16(lo)
        a0 = __dp2a_lo(hi0, 0x0100u, a0); a1 = __dp2a_lo(hi0, 0x0001u, a1);
        a2 = __dp2a_lo(lo0, 0x0100u, a2); a3 = __dp2a_lo(lo0, 0x0001u, a3);
        a0 = __dp2a_lo(hi1, 0x0100u, a0); a1 = __dp2a_lo(hi1, 0x0001u, a1);
        a2 = __dp2a_lo(lo1, 0x0100u, a2); a3 = __dp2a_lo(lo1, 0x0001u, a3);
        a0 = __dp2a_lo(hi2, 0x0100u, a0); a1 = __dp2a_lo(hi2, 0x0001u, a1);
        a2 = __dp2a_lo(lo2, 0x0100u, a2); a3 = __dp2a_lo(lo2, 0x0001u, a3);
        a0 = __dp2a_lo(hi3, 0x0100u, a0); a1 = __dp2a_lo(hi3, 0x0001u, a1);
        a2 = __dp2a_lo(lo3, 0x0100u, a2); a3 = __dp2a_lo(lo3, 0x0001u, a3);
    }
    for (; k < ke; ++k) {
        unsigned lo0, hi0;
        asm("ld.shared.v2.u32 {%0,%1},[%2];" : "=r"(lo0), "=r"(hi0) : "r"(tb + (unsigned)slist[k]));
        a0 = __dp2a_lo(hi0, 0x0100u, a0); a1 = __dp2a_lo(hi0, 0x0001u, a1);
        a2 = __dp2a_lo(lo0, 0x0100u, a2); a3 = __dp2a_lo(lo0, 0x0001u, a3);
    }

    // combine upper half into lower (exact integers, fixed order)
    if (isUp) *(uint4*)(comb + (tid - 512) * 4) = make_uint4(a0, a1, a2, a3);
    __syncthreads();
    if (isLow) {
        uint4 u = *(const uint4*)(comb + tid * 4);
        a0 += u.x; a1 += u.y; a2 += u.z; a3 += u.w;

        // slice partial of integer rowsum S for 4 outputs
        int i2a = (100 * s) / NSLICE;
        int i2b = (100 * (s + 1)) / NSLICE;
        unsigned S0 = 0, S1 = 0, S2 = 0, S3 = 0;
        for (int i2 = i2a; i2 < i2b; ++i2) {
            int di = i1 - i2; if (di < 0) di = -di;
            uint4 av = *(const uint4*)(c_tab.Ai + di * 100 + j1q);
            S0 += av.x; S1 += av.y; S2 += av.z; S3 += av.w;
        }
        int oq = o0 + 4 * q;
        atomicAdd(&g_Ti[oq],     a0);
        atomicAdd(&g_Ti[oq + 1], a1);
        atomicAdd(&g_Ti[oq + 2], a2);
        atomicAdd(&g_Ti[oq + 3], a3);
        atomicAdd(&g_Si[oq],     S0);
        atomicAdd(&g_Si[oq + 1], S1);
        atomicAdd(&g_Si[oq + 2], S2);
        atomicAdd(&g_Si[oq + 3], S3);
    }

    // ---- chunk-last block reduces its chunk (16KB), then zeroes it ----
    __threadfence();
    __syncthreads();
    if (tid == 0) {
        int fin = atomicAdd(&g_dc[chunk], 1);
        lastFlag = (fin == NSLICE - 1);
    }
    __syncthreads();
    if (lastFlag) {
        __threadfence();
        float ls = 0.f;
        if (tid < 1000) {
            int oT = chunk * OUTB + 2 * tid;
            uint2 ti = *(const uint2*)&g_Ti[oT];
            uint2 si = *(const uint2*)&g_Si[oT];
            float2 pr = *(const float2*)&prob[oT];
            float pxe = (pr.x >= 0.5f) ? 1.0f : 0.0f;
            float pxo = (pr.y >= 0.5f) ? 1.0f : 0.0f;
            float Te = __uint2float_rn(ti.x) * (float)(1.0 / QSCALE);
            float To = __uint2float_rn(ti.y) * (float)(1.0 / QSCALE);
            float Se = __uint2float_rn(si.x) * (float)(1.0 / SSCALE);
            float So = __uint2float_rn(si.y) * (float)(1.0 / SSCALE);
            ls = fabsf(pxe * Se - Te) + fabsf(pxo * So - To);
            *(uint2*)&g_Ti[oT] = make_uint2(0u, 0u);   // replay-safe self-clean
            *(uint2*)&g_Si[oT] = make_uint2(0u, 0u);
        }
        #pragma unroll
        for (int off = 16; off; off >>= 1)
            ls += __shfl_down_sync(0xffffffffu, ls, off);
        if (lane == 0) wsum[warp] = ls;
        __syncthreads();
        if (tid == 0) {
            float t = 0.f;
            #pragma unroll
            for (int w = 0; w < 32; ++w) t += wsum[w];
            g_cs[chunk] = t;
            g_dc[chunk] = 0;
            __threadfence();
            int fin2 = atomicAdd(&g_done2, 1);
            if (fin2 == NCHUNK - 1) {
                __threadfence();
                float tt = 0.f;
                #pragma unroll
                for (int c = 0; c < NCHUNK; ++c) tt += g_cs[c];
                out[0] = tt * (float)(1.0 / ((double)NN * (double)NN));
                g_done2 = 0;
                __threadfence();
            }
        }
    }
}

extern "C" void kernel_launch(void* const* d_in, const int* in_sizes, int n_in,
                              void* d_out, int out_size) {
    const float* prob = (const float*)d_in[0];
    const float* gt   = (const float*)d_in[1];
    float* out = (float*)d_out;

    cudaFuncSetAttribute(k_all, cudaFuncAttributeMaxDynamicSharedMemorySize, SMEM_BYTES);
    k_all<<<NB, NT, SMEM_BYTES>>>(prob, gt, out);
}